// round 6
// baseline (speedup 1.0000x reference)
#include <cuda_runtime.h>
#include <math.h>

#define NPTS 32768
#define D 64
#define K 64

// Per-cluster constants & whitened means (device globals: no allocation allowed)
__device__ float g_muP[K * D];
__device__ float g_cst[K];

// Accurate digamma in double: recurrence to x>=6, then asymptotic series.
__device__ double digamma_d(double x) {
    double r = 0.0;
    while (x < 6.0) { r -= 1.0 / x; x += 1.0; }
    double f = 1.0 / (x * x);
    r += log(x) - 0.5 / x
       - f * (1.0 / 12.0 - f * (1.0 / 120.0 - f * (1.0 / 252.0
       - f * (1.0 / 240.0 - f * (1.0 / 132.0)))));
    return r;
}

// One block, K threads: compute per-cluster constant and muP[k,:] = means[k] @ P_k.
// s0/s1 are the two 64-element inputs in encounter order; decide on-device which
// is degrees_of_freedom (values >= 65) and which is mean_precision (values <= 10).
__global__ void bgm_const_kernel(const float* __restrict__ means,
                                 const float* __restrict__ P,
                                 const float* __restrict__ wc,   // [2,K]
                                 const float* __restrict__ s0,
                                 const float* __restrict__ s1) {
    int k = threadIdx.x;
    if (k >= K) return;

    const float* dof = (s0[0] > 32.0f) ? s0 : s1;
    const float* mp  = (s0[0] > 32.0f) ? s1 : s0;

    // muP[k,e] = sum_d means[k,d] * P[k,d,e]
    for (int e = 0; e < D; e++) {
        float acc = 0.0f;
        for (int d = 0; d < D; d++)
            acc = fmaf(means[k * D + d], P[((size_t)k * D + d) * D + e], acc);
        g_muP[k * D + e] = acc;
    }

    // log|P_k| from diagonal
    double logdet = 0.0;
    for (int e = 0; e < D; e++)
        logdet += log((double)P[((size_t)k * D + e) * D + e]);

    double dofk = (double)dof[k];

    // log_lambda
    double ll = (double)D * log(2.0);
    for (int i = 0; i < D; i++)
        ll += digamma_d(0.5 * (dofk - (double)i));

    // stick-breaking log weight
    double a_k = (double)wc[k], b_k = (double)wc[K + k];
    double logw = digamma_d(a_k) - digamma_d(a_k + b_k);
    for (int j = 0; j < k; j++) {
        double a_j = (double)wc[j], b_j = (double)wc[K + j];
        logw += digamma_d(b_j) - digamma_d(a_j + b_j);
    }

    double cst = logdet
               - 0.5 * (double)D * log(dofk)
               + 0.5 * (ll - (double)D / (double)mp[k])
               + logw
               - 0.5 * (double)D * log(2.0 * M_PI);
    g_cst[k] = (float)cst;
}

// 256 blocks x 128 threads; one data row per thread, loop over clusters.
__global__ void __launch_bounds__(128)
bgm_argmax_kernel(const float* __restrict__ X,
                  const float* __restrict__ P,
                  float* __restrict__ out) {
    __shared__ float Ps[D * D];   // 16 KB: P_k staged per iteration
    __shared__ float mus[D];

    const int tid = threadIdx.x;
    const int n = blockIdx.x * 128 + tid;

    // Row of X in registers (16 x float4)
    float x[D];
    {
        const float4* Xv = (const float4*)(X + (size_t)n * D);
        #pragma unroll
        for (int i = 0; i < D / 4; i++) {
            float4 v = Xv[i];
            x[4 * i + 0] = v.x; x[4 * i + 1] = v.y;
            x[4 * i + 2] = v.z; x[4 * i + 3] = v.w;
        }
    }

    float best = -INFINITY;
    int besti = 0;

    for (int k = 0; k < K; k++) {
        // Cooperative stage of P_k (4096 floats) into shared: 8 x float4 per thread
        {
            const float4* Pv = (const float4*)(P + (size_t)k * D * D);
            float4* Psv = (float4*)Ps;
            #pragma unroll
            for (int i = 0; i < 8; i++)
                Psv[tid + 128 * i] = Pv[tid + 128 * i];
            if (tid < D) mus[tid] = g_muP[k * D + tid];
        }
        __syncthreads();

        // sq = || x @ P_k - muP_k ||^2, 8 output components in flight
        float sq = 0.0f;
        #pragma unroll 1
        for (int e = 0; e < D; e += 8) {
            float acc[8];
            #pragma unroll
            for (int j = 0; j < 8; j++) acc[j] = -mus[e + j];
            #pragma unroll
            for (int d = 0; d < D; d++) {
                float xd = x[d];
                float4 p0 = *(const float4*)&Ps[d * D + e];
                float4 p1 = *(const float4*)&Ps[d * D + e + 4];
                acc[0] = fmaf(xd, p0.x, acc[0]);
                acc[1] = fmaf(xd, p0.y, acc[1]);
                acc[2] = fmaf(xd, p0.z, acc[2]);
                acc[3] = fmaf(xd, p0.w, acc[3]);
                acc[4] = fmaf(xd, p1.x, acc[4]);
                acc[5] = fmaf(xd, p1.y, acc[5]);
                acc[6] = fmaf(xd, p1.z, acc[6]);
                acc[7] = fmaf(xd, p1.w, acc[7]);
            }
            #pragma unroll
            for (int j = 0; j < 8; j++) sq = fmaf(acc[j], acc[j], sq);
        }

        float val = g_cst[k] - 0.5f * sq;
        if (val > best) { best = val; besti = k; }   // strict > keeps first index on ties
        __syncthreads();
    }

    // Output dtype is float32 (argmax index as float).
    out[n] = (float)besti;
}

extern "C" void kernel_launch(void* const* d_in, const int* in_sizes, int n_in,
                              void* d_out, int out_size) {
    // Bind inputs BY ELEMENT COUNT (robust to harness input ordering):
    //   X: 32768*64 = 2097152, P: 64*64*64 = 262144, means: 64*64 = 4096,
    //   wc: 2*64 = 128, dof/mp: 64 each (disambiguated on-device by value).
    const float* X = 0; const float* P = 0; const float* means = 0;
    const float* wc = 0; const float* s0 = 0; const float* s1 = 0;
    for (int i = 0; i < n_in; i++) {
        const float* p = (const float*)d_in[i];
        switch (in_sizes[i]) {
            case 2097152: X = p; break;
            case 262144:  P = p; break;
            case 4096:    means = p; break;
            case 128:     wc = p; break;
            case 64:      if (!s0) s0 = p; else s1 = p; break;
            default: break;
        }
    }
    float* out = (float*)d_out;

    bgm_const_kernel<<<1, K>>>(means, P, wc, s0, s1);
    bgm_argmax_kernel<<<NPTS / 128, 128>>>(X, P, out);
}

// round 7
// speedup vs baseline: 2.3803x; 2.3803x over previous
#include <cuda_runtime.h>
#include <math.h>

#define NPTS 32768
#define D 64
#define K 64
#define KSPLIT 4
#define KPER (K / KSPLIT)

// Device globals (no allocation allowed anywhere)
__device__ float g_muP[K * D];
__device__ float g_cst[K];
__device__ unsigned long long g_best[NPTS];

// Accurate digamma in double: recurrence to x>=6, then asymptotic series.
__device__ double digamma_d(double x) {
    double r = 0.0;
    while (x < 6.0) { r -= 1.0 / x; x += 1.0; }
    double f = 1.0 / (x * x);
    r += log(x) - 0.5 / x
       - f * (1.0 / 12.0 - f * (1.0 / 120.0 - f * (1.0 / 252.0
       - f * (1.0 / 240.0 - f * (1.0 / 132.0)))));
    return r;
}

// 64 blocks (one per cluster k) x 64 threads (one per output dim e).
// Computes muP[k,:] coalesced and the per-cluster scalar constant via a
// shared-memory double reduction of per-lane digamma/log contributions.
__global__ void bgm_const_kernel(const float* __restrict__ means,
                                 const float* __restrict__ P,
                                 const float* __restrict__ wc,   // [2,K]
                                 const float* __restrict__ s0,
                                 const float* __restrict__ s1) {
    const int k = blockIdx.x;
    const int t = threadIdx.x;

    const float* dof = (s0[0] > 32.0f) ? s0 : s1;
    const float* mp  = (s0[0] > 32.0f) ? s1 : s0;

    // muP[k,t] = sum_d means[k,d] * P[k,d,t]  (coalesced across t)
    float acc = 0.0f;
    for (int d = 0; d < D; d++)
        acc = fmaf(means[k * D + d], P[((size_t)k * D + d) * D + t], acc);
    g_muP[k * D + t] = acc;

    const double dofk = (double)dof[k];

    // Per-lane contributions to the constant:
    double c = 0.0;
    c += log((double)P[((size_t)k * D + t) * D + t]);       // logdet
    c += 0.5 * digamma_d(0.5 * (dofk - (double)t));          // 0.5 * log_lambda digamma sum
    if (t < k) {                                             // stick-breaking prefix
        double a_j = (double)wc[t], b_j = (double)wc[K + t];
        c += digamma_d(b_j) - digamma_d(a_j + b_j);
    }

    __shared__ double sbuf[D];
    sbuf[t] = c;
    __syncthreads();
    #pragma unroll
    for (int s = D / 2; s > 0; s >>= 1) {
        if (t < s) sbuf[t] += sbuf[t + s];
        __syncthreads();
    }

    if (t == 0) {
        double a_k = (double)wc[k], b_k = (double)wc[K + k];
        double cst = sbuf[0]
                   + 0.5 * (double)D * log(2.0)                    // 0.5 * D*log2 from log_lambda
                   - 0.5 * (double)D * log(dofk)
                   - 0.5 * (double)D / (double)mp[k]
                   + digamma_d(a_k) - digamma_d(a_k + b_k)
                   - 0.5 * (double)D * log(2.0 * M_PI);
        g_cst[k] = (float)cst;
    }
}

__global__ void bgm_init_kernel() {
    int n = blockIdx.x * blockDim.x + threadIdx.x;
    if (n < NPTS) g_best[n] = 0ull;   // below any ordered-float candidate
}

__device__ __forceinline__ unsigned int ordered_bits(float f) {
    unsigned int b = __float_as_uint(f);
    return (b & 0x80000000u) ? ~b : (b | 0x80000000u);
}

// Grid (256, KSPLIT), block 128. blockIdx.x = point chunk, blockIdx.y = k quarter.
// Each block scans KPER clusters for 128 points and merges its best candidate
// into g_best via packed 64-bit atomicMax (exact first-max tie-break).
__global__ void __launch_bounds__(128)
bgm_argmax_kernel(const float* __restrict__ X,
                  const float* __restrict__ P) {
    __shared__ float Ps[D * D];
    __shared__ float mus[D];

    const int tid = threadIdx.x;
    const int n = blockIdx.x * 128 + tid;
    const int k0 = blockIdx.y * KPER;

    float x[D];
    {
        const float4* Xv = (const float4*)(X + (size_t)n * D);
        #pragma unroll
        for (int i = 0; i < D / 4; i++) {
            float4 v = Xv[i];
            x[4 * i + 0] = v.x; x[4 * i + 1] = v.y;
            x[4 * i + 2] = v.z; x[4 * i + 3] = v.w;
        }
    }

    float best = -INFINITY;
    int besti = k0;

    for (int kk = 0; kk < KPER; kk++) {
        const int k = k0 + kk;
        {
            const float4* Pv = (const float4*)(P + (size_t)k * D * D);
            float4* Psv = (float4*)Ps;
            #pragma unroll
            for (int i = 0; i < 8; i++)
                Psv[tid + 128 * i] = Pv[tid + 128 * i];
            if (tid < D) mus[tid] = g_muP[k * D + tid];
        }
        __syncthreads();

        float sq = 0.0f;
        #pragma unroll 1
        for (int e = 0; e < D; e += 8) {
            float acc[8];
            #pragma unroll
            for (int j = 0; j < 8; j++) acc[j] = -mus[e + j];
            #pragma unroll
            for (int d = 0; d < D; d++) {
                float xd = x[d];
                float4 p0 = *(const float4*)&Ps[d * D + e];
                float4 p1 = *(const float4*)&Ps[d * D + e + 4];
                acc[0] = fmaf(xd, p0.x, acc[0]);
                acc[1] = fmaf(xd, p0.y, acc[1]);
                acc[2] = fmaf(xd, p0.z, acc[2]);
                acc[3] = fmaf(xd, p0.w, acc[3]);
                acc[4] = fmaf(xd, p1.x, acc[4]);
                acc[5] = fmaf(xd, p1.y, acc[5]);
                acc[6] = fmaf(xd, p1.z, acc[6]);
                acc[7] = fmaf(xd, p1.w, acc[7]);
            }
            #pragma unroll
            for (int j = 0; j < 8; j++) sq = fmaf(acc[j], acc[j], sq);
        }

        float val = g_cst[k] - 0.5f * sq;
        if (val > best) { best = val; besti = k; }   // strict > keeps smallest k on ties
        __syncthreads();
    }

    // Pack (value, smallest-k-wins) and merge across the KSPLIT blocks.
    unsigned long long packed =
        ((unsigned long long)ordered_bits(best) << 32) | (unsigned int)(K - 1 - besti);
    atomicMax(&g_best[n], packed);
}

__global__ void bgm_final_kernel(float* __restrict__ out) {
    int n = blockIdx.x * blockDim.x + threadIdx.x;
    if (n < NPTS)
        out[n] = (float)(K - 1 - (int)(g_best[n] & 0xFFFFFFFFu));
}

extern "C" void kernel_launch(void* const* d_in, const int* in_sizes, int n_in,
                              void* d_out, int out_size) {
    // Bind inputs BY ELEMENT COUNT:
    //   X: 2097152, P: 262144, means: 4096, wc: 128, dof/mp: 64 each
    //   (dof vs mp disambiguated on-device by value range).
    const float* X = 0; const float* P = 0; const float* means = 0;
    const float* wc = 0; const float* s0 = 0; const float* s1 = 0;
    for (int i = 0; i < n_in; i++) {
        const float* p = (const float*)d_in[i];
        switch (in_sizes[i]) {
            case 2097152: X = p; break;
            case 262144:  P = p; break;
            case 4096:    means = p; break;
            case 128:     wc = p; break;
            case 64:      if (!s0) s0 = p; else s1 = p; break;
            default: break;
        }
    }
    float* out = (float*)d_out;

    bgm_const_kernel<<<K, D>>>(means, P, wc, s0, s1);
    bgm_init_kernel<<<NPTS / 256, 256>>>();
    dim3 grid(NPTS / 128, KSPLIT);
    bgm_argmax_kernel<<<grid, 128>>>(X, P);
    bgm_final_kernel<<<NPTS / 256, 256>>>(out);
}

// round 10
// speedup vs baseline: 2.4937x; 1.0476x over previous
#include <cuda_runtime.h>
#include <math.h>

#define NPTS 32768
#define D 64
#define K 64
#define KSPLIT 4
#define KPER (K / KSPLIT)

// Packed per-cluster data: 36 upper-tri 8x8 blocks (col-major within block,
// 2304 floats) + h vector (64 floats) + pad -> 2560 floats (10 KB) per cluster.
#define WSTRIDE 2560
#define H_OFF 2304

__device__ float g_W[K][WSTRIDE];
__device__ float g_c2[K];
__device__ unsigned long long g_best[NPTS];

// Packed block offset for upper-tri block (bi, bj), bj >= bi.
__host__ __device__ __forceinline__ int blkoff(int bi, int bj) {
    return (8 * bi - (bi * (bi - 1)) / 2) + (bj - bi);
}

// Accurate digamma in double: recurrence to x>=6, then asymptotic series.
__device__ double digamma_d(double x) {
    double r = 0.0;
    while (x < 6.0) { r -= 1.0 / x; x += 1.0; }
    double f = 1.0 / (x * x);
    r += log(x) - 0.5 / x
       - f * (1.0 / 12.0 - f * (1.0 / 120.0 - f * (1.0 / 252.0
       - f * (1.0 / 240.0 - f * (1.0 / 132.0)))));
    return r;
}

// 64 blocks (one per cluster) x 64 threads (one per row i).
// Computes S_k = P_k P_k^T upper triangle (packed, off-diag doubled),
// h_k = P_k @ muP_k, and c2_k = cst_k - 0.5*||muP_k||^2.
__global__ void bgm_const_kernel(const float* __restrict__ means,
                                 const float* __restrict__ P,
                                 const float* __restrict__ wc,   // [2,K]
                                 const float* __restrict__ s0,
                                 const float* __restrict__ s1) {
    const int k = blockIdx.x;
    const int i = threadIdx.x;   // row index 0..63

    const float* dof = (s0[0] > 32.0f) ? s0 : s1;
    const float* mp  = (s0[0] > 32.0f) ? s1 : s0;

    const float* Pk = P + (size_t)k * D * D;

    __shared__ float muP[D];
    __shared__ double sbuf[D];

    // muP[e] = sum_d means[k,d] * P[k,d,e]   (coalesced across threads e=i)
    {
        float acc = 0.0f;
        for (int d = 0; d < D; d++)
            acc = fmaf(means[k * D + d], Pk[d * D + i], acc);
        muP[i] = acc;
    }
    __syncthreads();

    // h_i = sum_e P[k,i,e] * muP[e]
    {
        float acc = 0.0f;
        for (int e = 0; e < D; e++)
            acc = fmaf(Pk[i * D + e], muP[e], acc);
        g_W[k][H_OFF + i] = acc;
    }

    // Row i of S: S_ij for j >= i (4 partial accumulators for ILP).
    {
        const int bi = i / 8, r = i % 8;
        // zero the sub-diagonal slots of the diagonal block for this row
        for (int j = 8 * bi; j < i; j++) {
            int c = j % 8;
            g_W[k][blkoff(bi, bi) * 64 + c * 8 + r] = 0.0f;
        }
        for (int j = i; j < D; j++) {
            float a0 = 0.f, a1 = 0.f, a2 = 0.f, a3 = 0.f;
            for (int e = 0; e < D; e += 4) {
                a0 = fmaf(Pk[i * D + e + 0], Pk[j * D + e + 0], a0);
                a1 = fmaf(Pk[i * D + e + 1], Pk[j * D + e + 1], a1);
                a2 = fmaf(Pk[i * D + e + 2], Pk[j * D + e + 2], a2);
                a3 = fmaf(Pk[i * D + e + 3], Pk[j * D + e + 3], a3);
            }
            float s = (a0 + a1) + (a2 + a3);
            float w = (j == i) ? s : 2.0f * s;
            int bj = j / 8, c = j % 8;
            g_W[k][blkoff(bi, bj) * 64 + c * 8 + r] = w;
        }
    }

    // Per-lane contributions to the scalar constant.
    const double dofk = (double)dof[k];
    double c = 0.0;
    c += log((double)Pk[i * D + i]);                      // logdet
    c += 0.5 * digamma_d(0.5 * (dofk - (double)i));       // 0.5 * digamma sum
    c -= 0.5 * (double)muP[i] * (double)muP[i];           // -0.5*||muP||^2
    if (i < k) {                                          // stick-breaking prefix
        double a_j = (double)wc[i], b_j = (double)wc[K + i];
        c += digamma_d(b_j) - digamma_d(a_j + b_j);
    }
    sbuf[i] = c;
    __syncthreads();
    #pragma unroll
    for (int s = D / 2; s > 0; s >>= 1) {
        if (i < s) sbuf[i] += sbuf[i + s];
        __syncthreads();
    }
    if (i == 0) {
        double a_k = (double)wc[k], b_k = (double)wc[K + k];
        double cst = sbuf[0]
                   + 0.5 * (double)D * log(2.0)
                   - 0.5 * (double)D * log(dofk)
                   - 0.5 * (double)D / (double)mp[k]
                   + digamma_d(a_k) - digamma_d(a_k + b_k)
                   - 0.5 * (double)D * log(2.0 * M_PI);
        g_c2[k] = (float)cst;
    }
}

__global__ void bgm_init_kernel() {
    int n = blockIdx.x * blockDim.x + threadIdx.x;
    if (n < NPTS) g_best[n] = 0ull;
}

__device__ __forceinline__ unsigned int ordered_bits(float f) {
    unsigned int b = __float_as_uint(f);
    return (b & 0x80000000u) ? ~b : (b | 0x80000000u);
}

// Grid (256, KSPLIT), block 128. val = c2 + x.h - 0.5 * x^T S x via packed
// upper-tri 8x8 blocks. Merge across k-quarters with packed 64-bit atomicMax.
__global__ void __launch_bounds__(128)
bgm_argmax_kernel(const float* __restrict__ X) {
    __shared__ float Ws[WSTRIDE];   // 10 KB

    const int tid = threadIdx.x;
    const int n = blockIdx.x * 128 + tid;
    const int k0 = blockIdx.y * KPER;

    float x[D];
    {
        const float4* Xv = (const float4*)(X + (size_t)n * D);
        #pragma unroll
        for (int i = 0; i < D / 4; i++) {
            float4 v = Xv[i];
            x[4 * i + 0] = v.x; x[4 * i + 1] = v.y;
            x[4 * i + 2] = v.z; x[4 * i + 3] = v.w;
        }
    }

    float best = -INFINITY;
    int besti = k0;

    for (int kk = 0; kk < KPER; kk++) {
        const int k = k0 + kk;

        // Stage packed W_k + h_k: 640 float4, 5 per thread.
        {
            const float4* src = (const float4*)g_W[k];
            float4* dst = (float4*)Ws;
            #pragma unroll
            for (int i = 0; i < 5; i++)
                dst[tid + 128 * i] = src[tid + 128 * i];
        }
        __syncthreads();

        // sq = x^T S x over upper-tri blocks (off-diag already doubled).
        float sq = 0.0f;
        #pragma unroll
        for (int bi = 0; bi < 8; bi++) {
            float t8[8];
            #pragma unroll
            for (int r = 0; r < 8; r++) t8[r] = 0.0f;
            #pragma unroll
            for (int bj = bi; bj < 8; bj++) {
                const float* w = &Ws[blkoff(bi, bj) * 64];
                #pragma unroll
                for (int c = 0; c < 8; c++) {
                    float xc = x[8 * bj + c];
                    float4 w0 = *(const float4*)&w[c * 8];
                    float4 w1 = *(const float4*)&w[c * 8 + 4];
                    t8[0] = fmaf(w0.x, xc, t8[0]);
                    t8[1] = fmaf(w0.y, xc, t8[1]);
                    t8[2] = fmaf(w0.z, xc, t8[2]);
                    t8[3] = fmaf(w0.w, xc, t8[3]);
                    t8[4] = fmaf(w1.x, xc, t8[4]);
                    t8[5] = fmaf(w1.y, xc, t8[5]);
                    t8[6] = fmaf(w1.z, xc, t8[6]);
                    t8[7] = fmaf(w1.w, xc, t8[7]);
                }
            }
            #pragma unroll
            for (int r = 0; r < 8; r++) sq = fmaf(x[8 * bi + r], t8[r], sq);
        }

        // dot = x . h
        float dot = 0.0f;
        #pragma unroll
        for (int e = 0; e < D; e += 8) {
            float4 h0 = *(const float4*)&Ws[H_OFF + e];
            float4 h1 = *(const float4*)&Ws[H_OFF + e + 4];
            dot = fmaf(x[e + 0], h0.x, dot);
            dot = fmaf(x[e + 1], h0.y, dot);
            dot = fmaf(x[e + 2], h0.z, dot);
            dot = fmaf(x[e + 3], h0.w, dot);
            dot = fmaf(x[e + 4], h1.x, dot);
            dot = fmaf(x[e + 5], h1.y, dot);
            dot = fmaf(x[e + 6], h1.z, dot);
            dot = fmaf(x[e + 7], h1.w, dot);
        }

        float val = g_c2[k] + dot - 0.5f * sq;
        if (val > best) { best = val; besti = k; }
        __syncthreads();
    }

    unsigned long long packed =
        ((unsigned long long)ordered_bits(best) << 32) | (unsigned int)(K - 1 - besti);
    atomicMax(&g_best[n], packed);
}

__global__ void bgm_final_kernel(float* __restrict__ out) {
    int n = blockIdx.x * blockDim.x + threadIdx.x;
    if (n < NPTS)
        out[n] = (float)(K - 1 - (int)(g_best[n] & 0xFFFFFFFFu));
}

extern "C" void kernel_launch(void* const* d_in, const int* in_sizes, int n_in,
                              void* d_out, int out_size) {
    // Bind inputs BY ELEMENT COUNT:
    //   X: 2097152, P: 262144, means: 4096, wc: 128, dof/mp: 64 each
    //   (dof vs mp disambiguated on-device by value range).
    const float* X = 0; const float* P = 0; const float* means = 0;
    const float* wc = 0; const float* s0 = 0; const float* s1 = 0;
    for (int i = 0; i < n_in; i++) {
        const float* p = (const float*)d_in[i];
        switch (in_sizes[i]) {
            case 2097152: X = p; break;
            case 262144:  P = p; break;
            case 4096:    means = p; break;
            case 128:     wc = p; break;
            case 64:      if (!s0) s0 = p; else s1 = p; break;
            default: break;
        }
    }
    float* out = (float*)d_out;

    bgm_const_kernel<<<K, D>>>(means, P, wc, s0, s1);
    bgm_init_kernel<<<NPTS / 256, 256>>>();
    dim3 grid(NPTS / 128, KSPLIT);
    bgm_argmax_kernel<<<grid, 128>>>(X);
    bgm_final_kernel<<<NPTS / 256, 256>>>(out);
}

// round 11
// speedup vs baseline: 2.8805x; 1.1551x over previous
#include <cuda_runtime.h>
#include <math.h>

#define NPTS 32768
#define D 64
#define K 64
#define KSPLIT 8
#define KPER (K / KSPLIT)

// Packed per-cluster data: 36 upper-tri 8x8 blocks (col-major within block,
// 2304 floats) + h vector (64 floats) + pad -> 2560 floats (10 KB) per cluster.
#define WSTRIDE 2560
#define H_OFF 2304

__device__ float g_W[K][WSTRIDE];
__device__ float g_c2[K];
__device__ unsigned long long g_best[NPTS];

__host__ __device__ __forceinline__ int blkoff(int bi, int bj) {
    return (8 * bi - (bi * (bi - 1)) / 2) + (bj - bi);
}

// Packed f32x2 FMA (Blackwell): d = a*b + d elementwise on {lo,hi} lanes.
#define FMA2(acc, a, b) \
    asm("fma.rn.f32x2 %0, %1, %2, %0;" : "+l"(acc) : "l"(a), "l"(b))
#define DUP2(d, f) do { unsigned int _u = __float_as_uint(f); \
    asm("mov.b64 %0, {%1, %1};" : "=l"(d) : "r"(_u)); } while (0)

// Accurate digamma in double: recurrence to x>=6, then asymptotic series.
__device__ double digamma_d(double x) {
    double r = 0.0;
    while (x < 6.0) { r -= 1.0 / x; x += 1.0; }
    double f = 1.0 / (x * x);
    r += log(x) - 0.5 / x
       - f * (1.0 / 12.0 - f * (1.0 / 120.0 - f * (1.0 / 252.0
       - f * (1.0 / 240.0 - f * (1.0 / 132.0)))));
    return r;
}

// 64 blocks (one per cluster) x 64 threads (one per row i).
__global__ void bgm_const_kernel(const float* __restrict__ means,
                                 const float* __restrict__ P,
                                 const float* __restrict__ wc,   // [2,K]
                                 const float* __restrict__ s0,
                                 const float* __restrict__ s1) {
    const int k = blockIdx.x;
    const int i = threadIdx.x;

    const float* dof = (s0[0] > 32.0f) ? s0 : s1;
    const float* mp  = (s0[0] > 32.0f) ? s1 : s0;

    const float* Pk = P + (size_t)k * D * D;

    __shared__ float muP[D];
    __shared__ double sbuf[D];

    {   // muP[e] = sum_d means[k,d] * P[k,d,e]
        float acc = 0.0f;
        for (int d = 0; d < D; d++)
            acc = fmaf(means[k * D + d], Pk[d * D + i], acc);
        muP[i] = acc;
    }
    __syncthreads();

    {   // h_i = sum_e P[k,i,e] * muP[e]
        float acc = 0.0f;
        for (int e = 0; e < D; e++)
            acc = fmaf(Pk[i * D + e], muP[e], acc);
        g_W[k][H_OFF + i] = acc;
    }

    {   // Row i of S = P P^T, upper triangle packed, off-diag doubled.
        const int bi = i / 8, r = i % 8;
        for (int j = 8 * bi; j < i; j++) {
            int c = j % 8;
            g_W[k][blkoff(bi, bi) * 64 + c * 8 + r] = 0.0f;
        }
        for (int j = i; j < D; j++) {
            float a0 = 0.f, a1 = 0.f, a2 = 0.f, a3 = 0.f;
            for (int e = 0; e < D; e += 4) {
                a0 = fmaf(Pk[i * D + e + 0], Pk[j * D + e + 0], a0);
                a1 = fmaf(Pk[i * D + e + 1], Pk[j * D + e + 1], a1);
                a2 = fmaf(Pk[i * D + e + 2], Pk[j * D + e + 2], a2);
                a3 = fmaf(Pk[i * D + e + 3], Pk[j * D + e + 3], a3);
            }
            float s = (a0 + a1) + (a2 + a3);
            float w = (j == i) ? s : 2.0f * s;
            int bj = j / 8, c = j % 8;
            g_W[k][blkoff(bi, bj) * 64 + c * 8 + r] = w;
        }
    }

    const double dofk = (double)dof[k];
    double c = 0.0;
    c += log((double)Pk[i * D + i]);
    c += 0.5 * digamma_d(0.5 * (dofk - (double)i));
    c -= 0.5 * (double)muP[i] * (double)muP[i];
    if (i < k) {
        double a_j = (double)wc[i], b_j = (double)wc[K + i];
        c += digamma_d(b_j) - digamma_d(a_j + b_j);
    }
    sbuf[i] = c;
    __syncthreads();
    #pragma unroll
    for (int s = D / 2; s > 0; s >>= 1) {
        if (i < s) sbuf[i] += sbuf[i + s];
        __syncthreads();
    }
    if (i == 0) {
        double a_k = (double)wc[k], b_k = (double)wc[K + k];
        double cst = sbuf[0]
                   + 0.5 * (double)D * log(2.0)
                   - 0.5 * (double)D * log(dofk)
                   - 0.5 * (double)D / (double)mp[k]
                   + digamma_d(a_k) - digamma_d(a_k + b_k)
                   - 0.5 * (double)D * log(2.0 * M_PI);
        g_c2[k] = (float)cst;
    }
}

__global__ void bgm_init_kernel() {
    int n = blockIdx.x * blockDim.x + threadIdx.x;
    if (n < NPTS) g_best[n] = 0ull;
}

__device__ __forceinline__ unsigned int ordered_bits(float f) {
    unsigned int b = __float_as_uint(f);
    return (b & 0x80000000u) ? ~b : (b | 0x80000000u);
}

// Grid (256, KSPLIT), 64 threads, 2 points per thread.
// val = c2 + x.h - 0.5 * x^T S x using f32x2 packed FMAs; W pairs come
// straight from LDS.128, each W load feeds both points.
__global__ void __launch_bounds__(64, 5)
bgm_argmax_kernel(const float* __restrict__ X) {
    __shared__ float Ws[WSTRIDE];   // 10 KB

    const int tid = threadIdx.x;
    const int n0 = blockIdx.x * 128 + tid;
    const int n1 = n0 + 64;
    const int k0 = blockIdx.y * KPER;

    float xa[D], xb[D];
    {
        const float4* A = (const float4*)(X + (size_t)n0 * D);
        const float4* B = (const float4*)(X + (size_t)n1 * D);
        #pragma unroll
        for (int i = 0; i < D / 4; i++) {
            float4 v = A[i];
            xa[4 * i] = v.x; xa[4 * i + 1] = v.y; xa[4 * i + 2] = v.z; xa[4 * i + 3] = v.w;
            float4 u = B[i];
            xb[4 * i] = u.x; xb[4 * i + 1] = u.y; xb[4 * i + 2] = u.z; xb[4 * i + 3] = u.w;
        }
    }

    float besta = -INFINITY, bestb = -INFINITY;
    int bia = k0, bib = k0;

    #pragma unroll 1
    for (int kk = 0; kk < KPER; kk++) {
        const int k = k0 + kk;

        {   // Stage packed W_k + h_k: 640 float4, 10 per thread.
            const float4* src = (const float4*)g_W[k];
            float4* dst = (float4*)Ws;
            #pragma unroll
            for (int i = 0; i < 10; i++)
                dst[tid + 64 * i] = src[tid + 64 * i];
        }
        __syncthreads();

        float sqa = 0.0f, sqb = 0.0f;
        #pragma unroll
        for (int bi = 0; bi < 8; bi++) {
            // f32x2 accumulators: tA[j] = {t8[2j], t8[2j+1]} for point a, same for b
            unsigned long long tA0 = 0, tA1 = 0, tA2 = 0, tA3 = 0;
            unsigned long long tB0 = 0, tB1 = 0, tB2 = 0, tB3 = 0;
            #pragma unroll
            for (int bj = bi; bj < 8; bj++) {
                const float* w = &Ws[blkoff(bi, bj) * 64];
                #pragma unroll
                for (int c = 0; c < 8; c++) {
                    unsigned long long xa2, xb2;
                    DUP2(xa2, xa[8 * bj + c]);
                    DUP2(xb2, xb[8 * bj + c]);
                    const ulonglong2* wv = (const ulonglong2*)&w[c * 8];
                    ulonglong2 w01 = wv[0];   // {w0,w1} {w2,w3}
                    ulonglong2 w23 = wv[1];   // {w4,w5} {w6,w7}
                    FMA2(tA0, w01.x, xa2);
                    FMA2(tA1, w01.y, xa2);
                    FMA2(tA2, w23.x, xa2);
                    FMA2(tA3, w23.y, xa2);
                    FMA2(tB0, w01.x, xb2);
                    FMA2(tB1, w01.y, xb2);
                    FMA2(tB2, w23.x, xb2);
                    FMA2(tB3, w23.y, xb2);
                }
            }
            // Unpack and finish in the same order as the scalar kernel.
            {
                unsigned int lo, hi;
                float tA[8], tB[8];
                asm("mov.b64 {%0,%1}, %2;" : "=r"(lo), "=r"(hi) : "l"(tA0)); tA[0]=__uint_as_float(lo); tA[1]=__uint_as_float(hi);
                asm("mov.b64 {%0,%1}, %2;" : "=r"(lo), "=r"(hi) : "l"(tA1)); tA[2]=__uint_as_float(lo); tA[3]=__uint_as_float(hi);
                asm("mov.b64 {%0,%1}, %2;" : "=r"(lo), "=r"(hi) : "l"(tA2)); tA[4]=__uint_as_float(lo); tA[5]=__uint_as_float(hi);
                asm("mov.b64 {%0,%1}, %2;" : "=r"(lo), "=r"(hi) : "l"(tA3)); tA[6]=__uint_as_float(lo); tA[7]=__uint_as_float(hi);
                asm("mov.b64 {%0,%1}, %2;" : "=r"(lo), "=r"(hi) : "l"(tB0)); tB[0]=__uint_as_float(lo); tB[1]=__uint_as_float(hi);
                asm("mov.b64 {%0,%1}, %2;" : "=r"(lo), "=r"(hi) : "l"(tB1)); tB[2]=__uint_as_float(lo); tB[3]=__uint_as_float(hi);
                asm("mov.b64 {%0,%1}, %2;" : "=r"(lo), "=r"(hi) : "l"(tB2)); tB[4]=__uint_as_float(lo); tB[5]=__uint_as_float(hi);
                asm("mov.b64 {%0,%1}, %2;" : "=r"(lo), "=r"(hi) : "l"(tB3)); tB[6]=__uint_as_float(lo); tB[7]=__uint_as_float(hi);
                #pragma unroll
                for (int r = 0; r < 8; r++) sqa = fmaf(xa[8 * bi + r], tA[r], sqa);
                #pragma unroll
                for (int r = 0; r < 8; r++) sqb = fmaf(xb[8 * bi + r], tB[r], sqb);
            }
        }

        // dot = x . h (same order as before: sequential e, one accumulator)
        float dota = 0.0f, dotb = 0.0f;
        #pragma unroll
        for (int e = 0; e < D; e += 4) {
            float4 h = *(const float4*)&Ws[H_OFF + e];
            dota = fmaf(xa[e + 0], h.x, dota);
            dota = fmaf(xa[e + 1], h.y, dota);
            dota = fmaf(xa[e + 2], h.z, dota);
            dota = fmaf(xa[e + 3], h.w, dota);
            dotb = fmaf(xb[e + 0], h.x, dotb);
            dotb = fmaf(xb[e + 1], h.y, dotb);
            dotb = fmaf(xb[e + 2], h.z, dotb);
            dotb = fmaf(xb[e + 3], h.w, dotb);
        }

        float c2 = g_c2[k];
        float va = c2 + dota - 0.5f * sqa;
        float vb = c2 + dotb - 0.5f * sqb;
        if (va > besta) { besta = va; bia = k; }
        if (vb > bestb) { bestb = vb; bib = k; }
        __syncthreads();
    }

    unsigned long long pa =
        ((unsigned long long)ordered_bits(besta) << 32) | (unsigned int)(K - 1 - bia);
    unsigned long long pb =
        ((unsigned long long)ordered_bits(bestb) << 32) | (unsigned int)(K - 1 - bib);
    atomicMax(&g_best[n0], pa);
    atomicMax(&g_best[n1], pb);
}

__global__ void bgm_final_kernel(float* __restrict__ out) {
    int n = blockIdx.x * blockDim.x + threadIdx.x;
    if (n < NPTS)
        out[n] = (float)(K - 1 - (int)(g_best[n] & 0xFFFFFFFFu));
}

extern "C" void kernel_launch(void* const* d_in, const int* in_sizes, int n_in,
                              void* d_out, int out_size) {
    // Bind inputs BY ELEMENT COUNT:
    //   X: 2097152, P: 262144, means: 4096, wc: 128, dof/mp: 64 each
    //   (dof vs mp disambiguated on-device by value range).
    const float* X = 0; const float* P = 0; const float* means = 0;
    const float* wc = 0; const float* s0 = 0; const float* s1 = 0;
    for (int i = 0; i < n_in; i++) {
        const float* p = (const float*)d_in[i];
        switch (in_sizes[i]) {
            case 2097152: X = p; break;
            case 262144:  P = p; break;
            case 4096:    means = p; break;
            case 128:     wc = p; break;
            case 64:      if (!s0) s0 = p; else s1 = p; break;
            default: break;
        }
    }
    float* out = (float*)d_out;

    bgm_const_kernel<<<K, D>>>(means, P, wc, s0, s1);
    bgm_init_kernel<<<NPTS / 256, 256>>>();
    dim3 grid(NPTS / 128, KSPLIT);
    bgm_argmax_kernel<<<grid, 64>>>(X);
    bgm_final_kernel<<<NPTS / 256, 256>>>(out);
}